// round 6
// baseline (speedup 1.0000x reference)
#include <cuda_runtime.h>

#define NN 50000
#define NE 800000
#define FD 64

// ---------------- scratch (static device globals; no runtime alloc) ----------------
__device__ float g_deg[NN];
__device__ float g_dinv[NN];
__device__ int   g_cnt[NN];
__device__ int   g_off[NN];    // bucket start (arbitrary order, bump-allocated)
__device__ int   g_end[NN];    // bucket end
__device__ int   g_cur[NN];
__device__ int   g_total;
__device__ __align__(16) int2  g_edge[NE];          // (src, weight-bits) bucketed by dst
__device__ __align__(16) float g_tx1[NN * FD];
__device__ __align__(16) float g_s2[NN * FD];
__device__ __align__(16) float g_wiA[FD * 2 * FD];  // interleaved (W0|W1) pairs
__device__ __align__(16) float g_wiB[FD * 2 * FD];  // (W2|U0)
__device__ __align__(16) float g_wiC[FD * 2 * FD];  // (U1|U2)
__device__ __align__(16) float g_wl[FD * FD];       // Wlin
__device__ float g_bias[3 * FD];                    // bz, bh, blin

typedef unsigned long long ull;

// ---------------- f32x2 packed helpers (sm_103a dual-fp32 datapath) ----------------
__device__ __forceinline__ void fma2(ull& d, ull a, ull b) {
    asm("fma.rn.f32x2 %0, %1, %2, %0;" : "+l"(d) : "l"(a), "l"(b));
}
__device__ __forceinline__ void unpk2(ull v, float& x, float& y) {
    asm("mov.b64 {%0, %1}, %2;" : "=f"(x), "=f"(y) : "l"(v));
}

// ---------------- CSR build ----------------
__global__ void k_zero() {
    int i = blockIdx.x * blockDim.x + threadIdx.x;
    if (i < NN) { g_deg[i] = 0.f; g_cnt[i] = 0; }
    if (i == 0) g_total = 0;
}

// 4 edges per thread, vector loads, fire-and-forget REDs
__global__ void k_hist(const int* __restrict__ src, const int* __restrict__ dst,
                       const float* __restrict__ ew) {
    int idx = blockIdx.x * blockDim.x + threadIdx.x;
    if (idx * 4 >= NE) return;
    int4   s4 = reinterpret_cast<const int4*>(src)[idx];
    int4   d4 = reinterpret_cast<const int4*>(dst)[idx];
    float4 w4 = reinterpret_cast<const float4*>(ew)[idx];
    atomicAdd(&g_deg[s4.x], w4.x); atomicAdd(&g_cnt[d4.x], 1);
    atomicAdd(&g_deg[s4.y], w4.y); atomicAdd(&g_cnt[d4.y], 1);
    atomicAdd(&g_deg[s4.z], w4.z); atomicAdd(&g_cnt[d4.z], 1);
    atomicAdd(&g_deg[s4.w], w4.w); atomicAdd(&g_cnt[d4.w], 1);
}

// dinv + bucket allocation (warp-aggregated bump allocator) + weight/bias prep
__global__ void k_prep(const float* __restrict__ Wxz, const float* __restrict__ bxz,
                       const float* __restrict__ bhz,
                       const float* __restrict__ Wxh, const float* __restrict__ bxh,
                       const float* __restrict__ bhh,
                       const float* __restrict__ Wlin, const float* __restrict__ blin) {
    int i = blockIdx.x * blockDim.x + threadIdx.x;
    int lane = threadIdx.x & 31;

    {   // bucket allocation: warp-scan counts, one atomic per warp
        int c = (i < NN) ? g_cnt[i] : 0;
        int scan = c;
        #pragma unroll
        for (int d = 1; d < 32; d <<= 1) {
            int v = __shfl_up_sync(0xFFFFFFFFu, scan, d);
            if (lane >= d) scan += v;
        }
        int warpsum = __shfl_sync(0xFFFFFFFFu, scan, 31);
        int base = 0;
        if (lane == 31 && warpsum > 0) base = atomicAdd(&g_total, warpsum);
        base = __shfl_sync(0xFFFFFFFFu, base, 31);
        if (i < NN) {
            int off = base + scan - c;
            g_off[i] = off;
            g_cur[i] = off;
            g_end[i] = off + c;
            float dg = g_deg[i];
            g_dinv[i] = (dg > 0.f) ? rsqrtf(dg) : 0.f;
        }
    }

    if (i < FD * FD) {
        // Tx2 = 2*S2 - Tx0  =>  fold into W0' = W0 - W2, W2' = 2*W2
        int k = i >> 6, f = i & 63, p = f >> 1, h = f & 1;
        float w0 = Wxz[i] - Wxz[8192 + i];
        float w1 = Wxz[4096 + i];
        float w2 = 2.f * Wxz[8192 + i];
        float u0 = Wxh[i] - Wxh[8192 + i];
        float u1 = Wxh[4096 + i];
        float u2 = 2.f * Wxh[8192 + i];
        int b = k * 128 + p * 4 + h;
        g_wiA[b] = w0; g_wiA[b + 2] = w1;
        g_wiB[b] = w2; g_wiB[b + 2] = u0;
        g_wiC[b] = u1; g_wiC[b + 2] = u2;
        g_wl[i] = Wlin[i];
    }
    if (i < FD) {
        g_bias[i]          = bxz[i] + bhz[i];   // H0=0 => cheb(H0)=b_hz
        g_bias[FD + i]     = bxh[i] + bhh[i];
        g_bias[2 * FD + i] = blin[i];
    }
}

// 4 edges per thread, vector loads, independent atomic->store chains (MLP 4)
__global__ void k_permute(const int* __restrict__ src, const int* __restrict__ dst,
                          const float* __restrict__ ew) {
    int idx = blockIdx.x * blockDim.x + threadIdx.x;
    if (idx * 4 >= NE) return;
    int4   s4 = reinterpret_cast<const int4*>(src)[idx];
    int4   d4 = reinterpret_cast<const int4*>(dst)[idx];
    float4 w4 = reinterpret_cast<const float4*>(ew)[idx];
    float c0 = -w4.x * g_dinv[s4.x] * g_dinv[d4.x];
    float c1 = -w4.y * g_dinv[s4.y] * g_dinv[d4.y];
    float c2 = -w4.z * g_dinv[s4.z] * g_dinv[d4.z];
    float c3 = -w4.w * g_dinv[s4.w] * g_dinv[d4.w];
    int p0 = atomicAdd(&g_cur[d4.x], 1);
    int p1 = atomicAdd(&g_cur[d4.y], 1);
    int p2 = atomicAdd(&g_cur[d4.z], 1);
    int p3 = atomicAdd(&g_cur[d4.w], 1);
    g_edge[p0] = make_int2(s4.x, __float_as_int(c0));
    g_edge[p1] = make_int2(s4.y, __float_as_int(c1));
    g_edge[p2] = make_int2(s4.z, __float_as_int(c2));
    g_edge[p3] = make_int2(s4.w, __float_as_int(c3));
}

// ---------------- gather passes: half-warp (16 lanes) per dst node ----------------
__device__ __forceinline__ void gather_body(const float4* __restrict__ in4,
                                            float4* __restrict__ out4) {
    int t = blockIdx.x * blockDim.x + threadIdx.x;
    int node = t >> 4, lane = t & 15;
    if (node >= NN) return;
    int beg = g_off[node], end = g_end[node];
    float4 a0 = make_float4(0.f, 0.f, 0.f, 0.f);
    float4 a1 = a0, a2 = a0, a3 = a0;
    int i = beg;
    for (; i + 3 < end; i += 4) {
        int2 e0 = g_edge[i], e1 = g_edge[i + 1], e2 = g_edge[i + 2], e3 = g_edge[i + 3];
        float4 v0 = in4[e0.x * 16 + lane];
        float4 v1 = in4[e1.x * 16 + lane];
        float4 v2 = in4[e2.x * 16 + lane];
        float4 v3 = in4[e3.x * 16 + lane];
        float w0 = __int_as_float(e0.y), w1 = __int_as_float(e1.y);
        float w2 = __int_as_float(e2.y), w3 = __int_as_float(e3.y);
        a0.x = fmaf(w0, v0.x, a0.x); a0.y = fmaf(w0, v0.y, a0.y);
        a0.z = fmaf(w0, v0.z, a0.z); a0.w = fmaf(w0, v0.w, a0.w);
        a1.x = fmaf(w1, v1.x, a1.x); a1.y = fmaf(w1, v1.y, a1.y);
        a1.z = fmaf(w1, v1.z, a1.z); a1.w = fmaf(w1, v1.w, a1.w);
        a2.x = fmaf(w2, v2.x, a2.x); a2.y = fmaf(w2, v2.y, a2.y);
        a2.z = fmaf(w2, v2.z, a2.z); a2.w = fmaf(w2, v2.w, a2.w);
        a3.x = fmaf(w3, v3.x, a3.x); a3.y = fmaf(w3, v3.y, a3.y);
        a3.z = fmaf(w3, v3.z, a3.z); a3.w = fmaf(w3, v3.w, a3.w);
    }
    for (; i < end; i++) {
        int2 e0 = g_edge[i];
        float w0 = __int_as_float(e0.y);
        float4 v0 = in4[e0.x * 16 + lane];
        a0.x = fmaf(w0, v0.x, a0.x); a0.y = fmaf(w0, v0.y, a0.y);
        a0.z = fmaf(w0, v0.z, a0.z); a0.w = fmaf(w0, v0.w, a0.w);
    }
    a0.x += a1.x + a2.x + a3.x;
    a0.y += a1.y + a2.y + a3.y;
    a0.z += a1.z + a2.z + a3.z;
    a0.w += a1.w + a2.w + a3.w;
    out4[node * 16 + lane] = a0;
}

__global__ void k_gather1(const float* __restrict__ x) {
    gather_body(reinterpret_cast<const float4*>(x),
                reinterpret_cast<float4*>(g_tx1));
}

__global__ void k_gather2() {
    gather_body(reinterpret_cast<const float4*>(g_tx1),
                reinterpret_cast<float4*>(g_s2));
}

// ---------------- fused dense kernel ----------------
// smem: 3 interleaved weight bufs (8192 ea) + Wlin (4096) + bias (192)
//       + duplicated activations sTxD (64 nodes * 388 floats).
// sTxD holds (t,t) pairs so the mainloop issues broadcast LDS.64 directly into
// FFMA2 operands (no MOV dup). H is stored duplicated into the same region.
#define TXD_STRIDE 388
#define SMEM_FLOATS (3 * 8192 + 4096 + 192 + 64 * TXD_STRIDE)

__global__ void __launch_bounds__(512, 1)
k_final(const float* __restrict__ x, float* __restrict__ out) {
    extern __shared__ float sm[];
    float* sWA  = sm;                  // 8192
    float* sWB  = sWA + 8192;          // 8192
    float* sWC  = sWB + 8192;          // 8192
    float* sWL  = sWC + 8192;          // 4096
    float* sB   = sWL + 4096;          // 192
    float* sTxD = sB + 192;            // 64 * 388 (dup pairs; reused for dup H)

    const int tid = threadIdx.x;
    for (int i = tid; i < 8192; i += 512) {
        sWA[i] = g_wiA[i]; sWB[i] = g_wiB[i]; sWC[i] = g_wiC[i];
    }
    for (int i = tid; i < 4096; i += 512) sWL[i] = g_wl[i];
    for (int i = tid; i < 192; i += 512) sB[i] = g_bias[i];

    const int warp = tid >> 5, lane = tid & 31;
    const int f = lane * 2, p = lane;
    const int ngroups = (NN + 63) / 64;

    for (int g = blockIdx.x; g < ngroups; g += gridDim.x) {
        const int base = g * 64;
        // stage rows for 64 nodes as duplicated pairs
        for (int i = tid; i < 1024; i += 512) {
            int node = i >> 4, q = i & 15;
            int n = base + node;
            float4 a, b, c;
            if (n < NN) {
                a = reinterpret_cast<const float4*>(x)[n * 16 + q];
                b = reinterpret_cast<const float4*>(g_tx1)[n * 16 + q];
                c = reinterpret_cast<const float4*>(g_s2)[n * 16 + q];
            } else {
                a = make_float4(0.f, 0.f, 0.f, 0.f); b = a; c = a;
            }
            float* dp = sTxD + node * TXD_STRIDE;
            *(float4*)&dp[8 * q]           = make_float4(a.x, a.x, a.y, a.y);
            *(float4*)&dp[8 * q + 4]       = make_float4(a.z, a.z, a.w, a.w);
            *(float4*)&dp[128 + 8 * q]     = make_float4(b.x, b.x, b.y, b.y);
            *(float4*)&dp[128 + 8 * q + 4] = make_float4(b.z, b.z, b.w, b.w);
            *(float4*)&dp[256 + 8 * q]     = make_float4(c.x, c.x, c.y, c.y);
            *(float4*)&dp[256 + 8 * q + 4] = make_float4(c.z, c.z, c.w, c.w);
        }
        __syncthreads();

        ull az[4], ah[4];
        {
            ull bz = *(const ull*)&sB[f];
            ull bh = *(const ull*)&sB[64 + f];
            #pragma unroll
            for (int j = 0; j < 4; j++) { az[j] = bz; ah[j] = bh; }
        }
        const float* t0 = sTxD + (warp * 4) * TXD_STRIDE;

        #pragma unroll 2
        for (int k = 0; k < 64; k++) {
            ulonglong2 wa = *(const ulonglong2*)&sWA[k * 128 + p * 4];
            ulonglong2 wb = *(const ulonglong2*)&sWB[k * 128 + p * 4];
            ulonglong2 wc = *(const ulonglong2*)&sWC[k * 128 + p * 4];
            #pragma unroll
            for (int j = 0; j < 4; j++) {
                const float* tj = t0 + j * TXD_STRIDE;
                ull a0 = *(const ull*)&tj[2 * k];
                ull a1 = *(const ull*)&tj[128 + 2 * k];
                ull a2 = *(const ull*)&tj[256 + 2 * k];
                fma2(az[j], a0, wa.x);
                fma2(az[j], a1, wa.y);
                fma2(az[j], a2, wb.x);
                fma2(ah[j], a0, wb.y);
                fma2(ah[j], a1, wc.x);
                fma2(ah[j], a2, wc.y);
            }
        }

        // gates in registers
        float Hx[4], Hy[4];
        #pragma unroll
        for (int j = 0; j < 4; j++) {
            float azx, azy, ahx, ahy;
            unpk2(az[j], azx, azy);
            unpk2(ah[j], ahx, ahy);
            float zx = 1.f / (1.f + __expf(-azx));
            float zy = 1.f / (1.f + __expf(-azy));
            float hx = 1.f - 2.f / (__expf(2.f * ahx) + 1.f);
            float hy = 1.f - 2.f / (__expf(2.f * ahy) + 1.f);
            Hx[j] = fmaxf((1.f - zx) * hx, 0.f);
            Hy[j] = fmaxf((1.f - zy) * hy, 0.f);
        }
        __syncthreads();  // all warps done reading sTxD

        // write duplicated H into reused region: node stride 128 floats
        #pragma unroll
        for (int j = 0; j < 4; j++) {
            int node = warp * 4 + j;
            *(float4*)&sTxD[node * 128 + 2 * f] =
                make_float4(Hx[j], Hx[j], Hy[j], Hy[j]);
        }
        __syncthreads();

        ull o[4];
        {
            ull bl = *(const ull*)&sB[128 + f];
            #pragma unroll
            for (int j = 0; j < 4; j++) o[j] = bl;
        }
        #pragma unroll 2
        for (int k = 0; k < 64; k++) {
            ull wl = *(const ull*)&sWL[k * 64 + f];
            #pragma unroll
            for (int j = 0; j < 4; j++) {
                ull hv = *(const ull*)&sTxD[(warp * 4 + j) * 128 + 2 * k];
                fma2(o[j], hv, wl);
            }
        }
        #pragma unroll
        for (int j = 0; j < 4; j++) {
            int n = base + warp * 4 + j;
            if (n < NN) {
                float ox, oy;
                unpk2(o[j], ox, oy);
                *(float2*)&out[n * 64 + f] = make_float2(ox, oy);
            }
        }
        __syncthreads();
    }
}

// ---------------- launch ----------------
extern "C" void kernel_launch(void* const* d_in, const int* in_sizes, int n_in,
                              void* d_out, int out_size) {
    const float* x    = (const float*)d_in[0];
    const int*   ei   = (const int*)d_in[1];
    const float* ew   = (const float*)d_in[2];
    const float* Wxz  = (const float*)d_in[3];
    const float* bxz  = (const float*)d_in[4];
    const float* bhz  = (const float*)d_in[6];   // W_hz unused (H0 = 0)
    const float* Wxh  = (const float*)d_in[11];
    const float* bxh  = (const float*)d_in[12];
    const float* bhh  = (const float*)d_in[14];  // W_hh unused
    const float* Wlin = (const float*)d_in[15];
    const float* blin = (const float*)d_in[16];
    float* out = (float*)d_out;

    const int* src = ei;
    const int* dst = ei + NE;

    cudaFuncSetAttribute(k_final, cudaFuncAttributeMaxDynamicSharedMemorySize,
                         SMEM_FLOATS * (int)sizeof(float));

    k_zero<<<(NN + 255) / 256, 256>>>();
    k_hist<<<(NE / 4 + 255) / 256, 256>>>(src, dst, ew);
    k_prep<<<(NN + 255) / 256, 256>>>(Wxz, bxz, bhz, Wxh, bxh, bhh, Wlin, blin);
    k_permute<<<(NE / 4 + 255) / 256, 256>>>(src, dst, ew);
    k_gather1<<<(NN * 16 + 255) / 256, 256>>>(x);
    k_gather2<<<(NN * 16 + 255) / 256, 256>>>();
    k_final<<<148, 512, SMEM_FLOATS * (int)sizeof(float)>>>(x, out);
}

// round 7
// speedup vs baseline: 1.1632x; 1.1632x over previous
#include <cuda_runtime.h>

#define NN 50000
#define NE 800000
#define FD 64

// ---------------- scratch (static device globals; no runtime alloc) ----------------
__device__ float g_deg[NN];
__device__ float g_dinv[NN];
__device__ int   g_cnt[NN];
__device__ int   g_off[NN];    // bucket start (arbitrary order, bump-allocated)
__device__ int   g_end[NN];    // bucket end
__device__ int   g_cur[NN];
__device__ int   g_total;
__device__ __align__(16) int2  g_edge[NE];          // (src, weight-bits) bucketed by dst
__device__ __align__(16) float g_tx1[NN * FD];
__device__ __align__(16) float g_s2[NN * FD];
__device__ __align__(16) float g_wc[7 * FD * FD];   // combined weights, [mat][k][f]
__device__ float g_bias[3 * FD];                    // bz, bh, blin

typedef unsigned long long ull;

// ---------------- f32x2 packed helpers (sm_103a dual-fp32 datapath) ----------------
__device__ __forceinline__ ull dup2(float a) {
    ull r;
    asm("mov.b64 %0, {%1, %1};" : "=l"(r) : "f"(a));
    return r;
}
__device__ __forceinline__ void fma2(ull& d, ull a, ull b) {
    asm("fma.rn.f32x2 %0, %1, %2, %0;" : "+l"(d) : "l"(a), "l"(b));
}
__device__ __forceinline__ void unpk2(ull v, float& x, float& y) {
    asm("mov.b64 {%0, %1}, %2;" : "=f"(x), "=f"(y) : "l"(v));
}

// ---------------- CSR build ----------------
__global__ void k_zero() {
    int i = blockIdx.x * blockDim.x + threadIdx.x;
    if (i < NN) { g_deg[i] = 0.f; g_cnt[i] = 0; }
    if (i == 0) g_total = 0;
}

// 4 edges per thread, vector loads, fire-and-forget REDs
__global__ void k_hist(const int* __restrict__ src, const int* __restrict__ dst,
                       const float* __restrict__ ew) {
    int idx = blockIdx.x * blockDim.x + threadIdx.x;
    if (idx * 4 >= NE) return;
    int4   s4 = reinterpret_cast<const int4*>(src)[idx];
    int4   d4 = reinterpret_cast<const int4*>(dst)[idx];
    float4 w4 = reinterpret_cast<const float4*>(ew)[idx];
    atomicAdd(&g_deg[s4.x], w4.x); atomicAdd(&g_cnt[d4.x], 1);
    atomicAdd(&g_deg[s4.y], w4.y); atomicAdd(&g_cnt[d4.y], 1);
    atomicAdd(&g_deg[s4.z], w4.z); atomicAdd(&g_cnt[d4.z], 1);
    atomicAdd(&g_deg[s4.w], w4.w); atomicAdd(&g_cnt[d4.w], 1);
}

// dinv + bucket allocation (warp-aggregated bump allocator, NO prefix scan)
// + weight combining + bias combining
__global__ void k_prep(const float* __restrict__ Wxz, const float* __restrict__ bxz,
                       const float* __restrict__ bhz,
                       const float* __restrict__ Wxh, const float* __restrict__ bxh,
                       const float* __restrict__ bhh,
                       const float* __restrict__ Wlin, const float* __restrict__ blin) {
    int i = blockIdx.x * blockDim.x + threadIdx.x;
    int lane = threadIdx.x & 31;

    {   // bucket allocation: warp-scan counts, one atomic per warp
        int c = (i < NN) ? g_cnt[i] : 0;
        int scan = c;
        #pragma unroll
        for (int d = 1; d < 32; d <<= 1) {
            int v = __shfl_up_sync(0xFFFFFFFFu, scan, d);
            if (lane >= d) scan += v;
        }
        int warpsum = __shfl_sync(0xFFFFFFFFu, scan, 31);
        int base = 0;
        if (lane == 31 && warpsum > 0) base = atomicAdd(&g_total, warpsum);
        base = __shfl_sync(0xFFFFFFFFu, base, 31);
        if (i < NN) {
            int off = base + scan - c;
            g_off[i] = off;
            g_cur[i] = off;
            g_end[i] = off + c;
            float dg = g_deg[i];
            g_dinv[i] = (dg > 0.f) ? rsqrtf(dg) : 0.f;
        }
    }

    if (i < FD * FD) {
        // Tx2 = 2*S2 - Tx0  =>  fold into W0' = W0 - W2, W2' = 2*W2
        g_wc[0 * 4096 + i] = Wxz[i] - Wxz[2 * 4096 + i];
        g_wc[1 * 4096 + i] = Wxz[4096 + i];
        g_wc[2 * 4096 + i] = 2.f * Wxz[2 * 4096 + i];
        g_wc[3 * 4096 + i] = Wxh[i] - Wxh[2 * 4096 + i];
        g_wc[4 * 4096 + i] = Wxh[4096 + i];
        g_wc[5 * 4096 + i] = 2.f * Wxh[2 * 4096 + i];
        g_wc[6 * 4096 + i] = Wlin[i];
    }
    if (i < FD) {
        g_bias[i]          = bxz[i] + bhz[i];   // H0=0 => cheb(H0)=b_hz
        g_bias[FD + i]     = bxh[i] + bhh[i];
        g_bias[2 * FD + i] = blin[i];
    }
}

// 4 edges per thread, vector loads, independent atomic->store chains (MLP 4)
__global__ void k_permute(const int* __restrict__ src, const int* __restrict__ dst,
                          const float* __restrict__ ew) {
    int idx = blockIdx.x * blockDim.x + threadIdx.x;
    if (idx * 4 >= NE) return;
    int4   s4 = reinterpret_cast<const int4*>(src)[idx];
    int4   d4 = reinterpret_cast<const int4*>(dst)[idx];
    float4 w4 = reinterpret_cast<const float4*>(ew)[idx];
    float c0 = -w4.x * g_dinv[s4.x] * g_dinv[d4.x];
    float c1 = -w4.y * g_dinv[s4.y] * g_dinv[d4.y];
    float c2 = -w4.z * g_dinv[s4.z] * g_dinv[d4.z];
    float c3 = -w4.w * g_dinv[s4.w] * g_dinv[d4.w];
    int p0 = atomicAdd(&g_cur[d4.x], 1);
    int p1 = atomicAdd(&g_cur[d4.y], 1);
    int p2 = atomicAdd(&g_cur[d4.z], 1);
    int p3 = atomicAdd(&g_cur[d4.w], 1);
    g_edge[p0] = make_int2(s4.x, __float_as_int(c0));
    g_edge[p1] = make_int2(s4.y, __float_as_int(c1));
    g_edge[p2] = make_int2(s4.z, __float_as_int(c2));
    g_edge[p3] = make_int2(s4.w, __float_as_int(c3));
}

// ---------------- gather passes: half-warp (16 lanes) per dst node ----------------
__device__ __forceinline__ void gather_body(const float4* __restrict__ in4,
                                            float4* __restrict__ out4) {
    int t = blockIdx.x * blockDim.x + threadIdx.x;
    int node = t >> 4, lane = t & 15;
    if (node >= NN) return;
    int beg = g_off[node], end = g_end[node];
    float4 a0 = make_float4(0.f, 0.f, 0.f, 0.f);
    float4 a1 = a0, a2 = a0, a3 = a0;
    int i = beg;
    for (; i + 3 < end; i += 4) {
        int2 e0 = g_edge[i], e1 = g_edge[i + 1], e2 = g_edge[i + 2], e3 = g_edge[i + 3];
        float4 v0 = in4[e0.x * 16 + lane];
        float4 v1 = in4[e1.x * 16 + lane];
        float4 v2 = in4[e2.x * 16 + lane];
        float4 v3 = in4[e3.x * 16 + lane];
        float w0 = __int_as_float(e0.y), w1 = __int_as_float(e1.y);
        float w2 = __int_as_float(e2.y), w3 = __int_as_float(e3.y);
        a0.x = fmaf(w0, v0.x, a0.x); a0.y = fmaf(w0, v0.y, a0.y);
        a0.z = fmaf(w0, v0.z, a0.z); a0.w = fmaf(w0, v0.w, a0.w);
        a1.x = fmaf(w1, v1.x, a1.x); a1.y = fmaf(w1, v1.y, a1.y);
        a1.z = fmaf(w1, v1.z, a1.z); a1.w = fmaf(w1, v1.w, a1.w);
        a2.x = fmaf(w2, v2.x, a2.x); a2.y = fmaf(w2, v2.y, a2.y);
        a2.z = fmaf(w2, v2.z, a2.z); a2.w = fmaf(w2, v2.w, a2.w);
        a3.x = fmaf(w3, v3.x, a3.x); a3.y = fmaf(w3, v3.y, a3.y);
        a3.z = fmaf(w3, v3.z, a3.z); a3.w = fmaf(w3, v3.w, a3.w);
    }
    for (; i < end; i++) {
        int2 e0 = g_edge[i];
        float w0 = __int_as_float(e0.y);
        float4 v0 = in4[e0.x * 16 + lane];
        a0.x = fmaf(w0, v0.x, a0.x); a0.y = fmaf(w0, v0.y, a0.y);
        a0.z = fmaf(w0, v0.z, a0.z); a0.w = fmaf(w0, v0.w, a0.w);
    }
    a0.x += a1.x + a2.x + a3.x;
    a0.y += a1.y + a2.y + a3.y;
    a0.z += a1.z + a2.z + a3.z;
    a0.w += a1.w + a2.w + a3.w;
    out4[node * 16 + lane] = a0;
}

__global__ void k_gather1(const float* __restrict__ x) {
    gather_body(reinterpret_cast<const float4*>(x),
                reinterpret_cast<float4*>(g_tx1));
}

__global__ void k_gather2() {
    gather_body(reinterpret_cast<const float4*>(g_tx1),
                reinterpret_cast<float4*>(g_s2));
}

// ---------------- fused dense kernel (proven 170us version) ----------------
#define SMEM_FLOATS (7 * 4096 + 192 + 64 * 192 + 64 * 64)

__global__ void __launch_bounds__(512, 1)
k_final(const float* __restrict__ x, float* __restrict__ out) {
    extern __shared__ float sm[];
    float* sW  = sm;                // 7*4096
    float* sB  = sW + 7 * 4096;    // 192
    float* sTx = sB + 192;         // 64 nodes * (Tx0|Tx1|S2) * 64
    float* sH  = sTx + 64 * 192;   // 64 nodes * 64

    const int tid = threadIdx.x;
    for (int i = tid; i < 7 * 4096; i += 512) sW[i] = g_wc[i];
    for (int i = tid; i < 192; i += 512) sB[i] = g_bias[i];

    const int warp = tid >> 5, lane = tid & 31;
    const int f = lane * 2;
    const int ngroups = (NN + 63) / 64;

    for (int g = blockIdx.x; g < ngroups; g += gridDim.x) {
        const int base = g * 64;
        for (int i = tid; i < 1024; i += 512) {
            int node = i >> 4, q = i & 15;
            int n = base + node;
            float4 a, b, c;
            if (n < NN) {
                a = reinterpret_cast<const float4*>(x)[n * 16 + q];
                b = reinterpret_cast<const float4*>(g_tx1)[n * 16 + q];
                c = reinterpret_cast<const float4*>(g_s2)[n * 16 + q];
            } else {
                a = make_float4(0.f, 0.f, 0.f, 0.f); b = a; c = a;
            }
            reinterpret_cast<float4*>(sTx)[node * 48 + q]      = a;
            reinterpret_cast<float4*>(sTx)[node * 48 + 16 + q] = b;
            reinterpret_cast<float4*>(sTx)[node * 48 + 32 + q] = c;
        }
        __syncthreads();

        ull az[4], ah[4];
        {
            ull bz = *(const ull*)&sB[f];
            ull bh = *(const ull*)&sB[64 + f];
            #pragma unroll
            for (int j = 0; j < 4; j++) { az[j] = bz; ah[j] = bh; }
        }
        const float* t = sTx + (warp * 4) * 192;

        #pragma unroll 4
        for (int k = 0; k < 64; k++) {
            ull w0 = *(const ull*)&sW[k * 64 + f];
            ull w1 = *(const ull*)&sW[4096 + k * 64 + f];
            ull w2 = *(const ull*)&sW[8192 + k * 64 + f];
            ull u0 = *(const ull*)&sW[12288 + k * 64 + f];
            ull u1 = *(const ull*)&sW[16384 + k * 64 + f];
            ull u2 = *(const ull*)&sW[20480 + k * 64 + f];
            #pragma unroll
            for (int j = 0; j < 4; j++) {
                ull a0 = dup2(t[j * 192 + k]);
                ull a1 = dup2(t[j * 192 + 64 + k]);
                ull a2 = dup2(t[j * 192 + 128 + k]);
                fma2(az[j], a0, w0);
                fma2(az[j], a1, w1);
                fma2(az[j], a2, w2);
                fma2(ah[j], a0, u0);
                fma2(ah[j], a1, u1);
                fma2(ah[j], a2, u2);
            }
        }

        #pragma unroll
        for (int j = 0; j < 4; j++) {
            int node = warp * 4 + j;
            float azx, azy, ahx, ahy;
            unpk2(az[j], azx, azy);
            unpk2(ah[j], ahx, ahy);
            float zx = 1.f / (1.f + __expf(-azx));
            float zy = 1.f / (1.f + __expf(-azy));
            float hx = 1.f - 2.f / (__expf(2.f * ahx) + 1.f);
            float hy = 1.f - 2.f / (__expf(2.f * ahy) + 1.f);
            sH[node * 64 + f]     = fmaxf((1.f - zx) * hx, 0.f);
            sH[node * 64 + f + 1] = fmaxf((1.f - zy) * hy, 0.f);
        }
        __syncthreads();

        ull o[4];
        {
            ull bl = *(const ull*)&sB[128 + f];
            #pragma unroll
            for (int j = 0; j < 4; j++) o[j] = bl;
        }
        #pragma unroll 4
        for (int k = 0; k < 64; k++) {
            ull wl = *(const ull*)&sW[6 * 4096 + k * 64 + f];
            #pragma unroll
            for (int j = 0; j < 4; j++) {
                ull hv = dup2(sH[(warp * 4 + j) * 64 + k]);
                fma2(o[j], hv, wl);
            }
        }
        #pragma unroll
        for (int j = 0; j < 4; j++) {
            int n = base + warp * 4 + j;
            if (n < NN) {
                float ox, oy;
                unpk2(o[j], ox, oy);
                *(float2*)&out[n * 64 + f] = make_float2(ox, oy);
            }
        }
        __syncthreads();
    }
}

// ---------------- launch ----------------
extern "C" void kernel_launch(void* const* d_in, const int* in_sizes, int n_in,
                              void* d_out, int out_size) {
    const float* x    = (const float*)d_in[0];
    const int*   ei   = (const int*)d_in[1];
    const float* ew   = (const float*)d_in[2];
    const float* Wxz  = (const float*)d_in[3];
    const float* bxz  = (const float*)d_in[4];
    const float* bhz  = (const float*)d_in[6];   // W_hz unused (H0 = 0)
    const float* Wxh  = (const float*)d_in[11];
    const float* bxh  = (const float*)d_in[12];
    const float* bhh  = (const float*)d_in[14];  // W_hh unused
    const float* Wlin = (const float*)d_in[15];
    const float* blin = (const float*)d_in[16];
    float* out = (float*)d_out;

    const int* src = ei;
    const int* dst = ei + NE;

    cudaFuncSetAttribute(k_final, cudaFuncAttributeMaxDynamicSharedMemorySize,
                         SMEM_FLOATS * (int)sizeof(float));

    k_zero<<<(NN + 255) / 256, 256>>>();
    k_hist<<<(NE / 4 + 255) / 256, 256>>>(src, dst, ew);
    k_prep<<<(NN + 255) / 256, 256>>>(Wxz, bxz, bhz, Wxh, bxh, bhh, Wlin, blin);
    k_permute<<<(NE / 4 + 255) / 256, 256>>>(src, dst, ew);
    k_gather1<<<(NN * 16 + 255) / 256, 256>>>(x);
    k_gather2<<<(NN * 16 + 255) / 256, 256>>>();
    k_final<<<148, 512, SMEM_FLOATS * (int)sizeof(float)>>>(x, out);
}